// round 1
// baseline (speedup 1.0000x reference)
#include <cuda_runtime.h>
#include <cstdint>

#define T_LEN 131072
#define D_X 16
#define D_L 8

// d_out layout (flat concat of reference tuple, all float32)
#define OFF_RECON 0
#define OFF_PRED  (T_LEN * D_X)                 // 2,097,152
#define OFF_LMP   (2 * T_LEN * D_X)             // 4,194,304
#define OFF_LVP   (OFF_LMP + 2 * T_LEN * D_L)   // 6,291,456
#define OFF_CT    (OFF_LVP + 2 * T_LEN * D_L)   // 8,388,608
#define OFF_CT1   (OFF_CT + T_LEN * D_X * D_L)  // 25,165,824

// ---------------------------------------------------------------------------
// Packed fp32x2 FMA (Blackwell): one instruction, two fp32 FMAs.
// ---------------------------------------------------------------------------
__device__ __forceinline__ float2 ffma2(float2 a, float2 b, float2 c) {
    float2 d;
    asm("{\n\t"
        ".reg .b64 ra, rb, rc, rd;\n\t"
        "mov.b64 ra, {%2, %3};\n\t"
        "mov.b64 rb, {%4, %5};\n\t"
        "mov.b64 rc, {%6, %7};\n\t"
        "fma.rn.f32x2 rd, ra, rb, rc;\n\t"
        "mov.b64 {%0, %1}, rd;\n\t"
        "}"
        : "=f"(d.x), "=f"(d.y)
        : "f"(a.x), "f"(a.y), "f"(b.x), "f"(b.y), "f"(c.x), "f"(c.y));
    return d;
}

// ---------------------------------------------------------------------------
// Preprocessed decoder weights (device-global scratch; no allocation).
// g_w0t: layer0 weights transposed to [n][j][k]  (n=node, j=hidden, k=feature)
// g_w12: collapsed (lw1 @ lw2)[n][f]  -> decode becomes 32->64->1
// g_beff: (lb1 @ lw2 + lb2)[n]
// ---------------------------------------------------------------------------
__device__ __align__(16) float g_w0t[D_X * 64 * 32];
__device__ __align__(16) float g_w12[D_X * 64];
__device__ __align__(16) float g_beff[D_X];

__global__ void prep_kernel(const float* __restrict__ lw0,
                            const float* __restrict__ lw1,
                            const float* __restrict__ lw2,
                            const float* __restrict__ lb1,
                            const float* __restrict__ lb2) {
    int tid = threadIdx.x;          // 1024 threads: (n, j)
    int n = tid >> 6;
    int j = tid & 63;
    // transpose lw0[n][f][j] -> g_w0t[n][j][f]
#pragma unroll
    for (int f = 0; f < 32; f++)
        g_w0t[(n * 64 + j) * 32 + f] = lw0[(n * 32 + f) * 64 + j];
    // w12[n][j] = sum_o lw1[n][j][o] * lw2[n][o]
    float acc = 0.f;
#pragma unroll 8
    for (int o = 0; o < 64; o++)
        acc = fmaf(lw1[(n * 64 + j) * 64 + o], lw2[n * 64 + o], acc);
    g_w12[n * 64 + j] = acc;
    if (j == 0) {
        float b = lb2[n];
        for (int o = 0; o < 64; o++)
            b = fmaf(lb1[n * 64 + o], lw2[n * 64 + o], b);
        g_beff[n] = b;
    }
}

// ---------------------------------------------------------------------------
// Encoder kernel: Ct (binarized) and Ct_1 (continuous), written into d_out.
// MLP: 1 -> 8 -> 8 -> 128, leaky_relu(0.01) on first two layers.
// ---------------------------------------------------------------------------
// smem layout per branch: w0[8] b0[8] w1[64] b1[8] w2[1024] b2[128] = 1240 floats
#define EW0 0
#define EB0 8
#define EW1 16
#define EB1 80
#define EW2 88
#define EB2 1112
#define ESZ 1240

__device__ __forceinline__ void enc_branch(float s, const float* __restrict__ w,
                                           float* __restrict__ dst, bool binarize) {
    float h0[8], h1[8];
#pragma unroll
    for (int i = 0; i < 8; i++) {
        float v = fmaf(s, w[EW0 + i], w[EB0 + i]);
        h0[i] = v > 0.f ? v : 0.01f * v;
    }
#pragma unroll
    for (int j = 0; j < 8; j++) {
        float a = 0.f;
#pragma unroll
        for (int i = 0; i < 8; i++) a = fmaf(h0[i], w[EW1 + i * 8 + j], a);
        a += w[EB1 + j];
        h1[j] = a > 0.f ? a : 0.01f * a;
    }
#pragma unroll 4
    for (int m = 0; m < 128; m += 4) {
        float4 a = make_float4(0.f, 0.f, 0.f, 0.f);
#pragma unroll
        for (int j = 0; j < 8; j++) {
            float4 ww = *(const float4*)&w[EW2 + j * 128 + m];
            a.x = fmaf(h1[j], ww.x, a.x);
            a.y = fmaf(h1[j], ww.y, a.y);
            a.z = fmaf(h1[j], ww.z, a.z);
            a.w = fmaf(h1[j], ww.w, a.w);
        }
        a.x += w[EB2 + m + 0];
        a.y += w[EB2 + m + 1];
        a.z += w[EB2 + m + 2];
        a.w += w[EB2 + m + 3];
        if (binarize) {
            a.x = a.x < 0.1f ? 0.f : 1.f;
            a.y = a.y < 0.1f ? 0.f : 1.f;
            a.z = a.z < 0.1f ? 0.f : 1.f;
            a.w = a.w < 0.1f ? 0.f : 1.f;
        }
        *(float4*)&dst[m] = a;
    }
}

__global__ void enc_kernel(const float* __restrict__ Tin,
                           const float* cw0, const float* cb0, const float* cw1,
                           const float* cb1, const float* cw2, const float* cb2,
                           const float* pw0, const float* pb0, const float* pw1,
                           const float* pb1, const float* pw2, const float* pb2,
                           float* __restrict__ out) {
    __shared__ __align__(16) float s_c[ESZ];
    __shared__ __align__(16) float s_p[ESZ];
    int tid = threadIdx.x;
    for (int i = tid; i < ESZ; i += blockDim.x) {
        float v, u;
        if (i < 8)         { v = cw0[i];        u = pw0[i];        }
        else if (i < 16)   { v = cb0[i - 8];    u = pb0[i - 8];    }
        else if (i < 80)   { v = cw1[i - 16];   u = pw1[i - 16];   }
        else if (i < 88)   { v = cb1[i - 80];   u = pb1[i - 80];   }
        else if (i < 1112) { v = cw2[i - 88];   u = pw2[i - 88];   }
        else               { v = cb2[i - 1112]; u = pb2[i - 1112]; }
        s_c[i] = v;
        s_p[i] = u;
    }
    __syncthreads();
    int t = blockIdx.x * blockDim.x + tid;
    if (t >= T_LEN) return;
    float s = Tin[t];
    enc_branch(s, s_c, out + OFF_CT + t * 128, true);
    enc_branch(s, s_p, out + OFF_CT1 + t * 128, false);
}

// ---------------------------------------------------------------------------
// Head kernel: lm_pred / lv_pred = relu(x @ W1 + b1) @ W2 + b2   (8->128->8)
// ---------------------------------------------------------------------------
__device__ __forceinline__ void head_fn(const float* __restrict__ x8,
                                        const float* __restrict__ w1t,  // [j][k]
                                        const float* __restrict__ b1,
                                        const float* __restrict__ w2,   // [j][o]
                                        const float* __restrict__ b2,
                                        float* __restrict__ dst) {
    float4 xa = *(const float4*)&x8[0];
    float4 xb = *(const float4*)&x8[4];
    float2 xx0 = make_float2(xa.x, xa.y), xx1 = make_float2(xa.z, xa.w);
    float2 xx2 = make_float2(xb.x, xb.y), xx3 = make_float2(xb.z, xb.w);
    float4 b2a = *(const float4*)&b2[0];
    float4 b2b = *(const float4*)&b2[4];
    float2 o0 = make_float2(b2a.x, b2a.y), o1 = make_float2(b2a.z, b2a.w);
    float2 o2 = make_float2(b2b.x, b2b.y), o3 = make_float2(b2b.z, b2b.w);
    const float2 zz = make_float2(0.f, 0.f);
#pragma unroll 4
    for (int j = 0; j < 128; j++) {
        float4 wA = *(const float4*)&w1t[j * 8];
        float4 wB = *(const float4*)&w1t[j * 8 + 4];
        float2 a0 = ffma2(xx0, make_float2(wA.x, wA.y), zz);
        float2 a1 = ffma2(xx2, make_float2(wB.x, wB.y), zz);
        a0 = ffma2(xx1, make_float2(wA.z, wA.w), a0);
        a1 = ffma2(xx3, make_float2(wB.z, wB.w), a1);
        float h = a0.x + a0.y + a1.x + a1.y + b1[j];
        h = fmaxf(h, 0.f);
        float2 hh = make_float2(h, h);
        float4 u = *(const float4*)&w2[j * 8];
        float4 v = *(const float4*)&w2[j * 8 + 4];
        o0 = ffma2(hh, make_float2(u.x, u.y), o0);
        o1 = ffma2(hh, make_float2(u.z, u.w), o1);
        o2 = ffma2(hh, make_float2(v.x, v.y), o2);
        o3 = ffma2(hh, make_float2(v.z, v.w), o3);
    }
    *(float4*)&dst[0] = make_float4(o0.x, o0.y, o1.x, o1.y);
    *(float4*)&dst[4] = make_float4(o2.x, o2.y, o3.x, o3.y);
}

__global__ void head_kernel(const float* __restrict__ lm,
                            const float* __restrict__ lv,
                            const float* fmw1, const float* fmb1,
                            const float* fmw2, const float* fmb2,
                            const float* fvw1, const float* fvb1,
                            const float* fvw2, const float* fvb2,
                            float* __restrict__ out) {
    __shared__ __align__(16) float sm_w1t[1024], sm_b1[128], sm_w2[1024], sm_b2[8];
    __shared__ __align__(16) float sv_w1t[1024], sv_b1[128], sv_w2[1024], sv_b2[8];
    int tid = threadIdx.x;
    for (int i = tid; i < 1024; i += blockDim.x) {
        int j = i >> 3, k = i & 7;
        sm_w1t[i] = fmw1[k * 128 + j];   // transpose
        sv_w1t[i] = fvw1[k * 128 + j];
        sm_w2[i] = fmw2[i];
        sv_w2[i] = fvw2[i];
    }
    if (tid < 128) { sm_b1[tid] = fmb1[tid]; sv_b1[tid] = fvb1[tid]; }
    if (tid < 8)   { sm_b2[tid] = fmb2[tid]; sv_b2[tid] = fvb2[tid]; }
    __syncthreads();
    int r = blockIdx.x * blockDim.x + tid;   // r in [0, 2*T_LEN)
    if (r >= 2 * T_LEN) return;
    head_fn(lm + r * 8, sm_w1t, sm_b1, sm_w2, sm_b2, out + OFF_LMP + r * 8);
    head_fn(lv + r * 8, sv_w1t, sv_b1, sv_w2, sv_b2, out + OFF_LVP + r * 8);
}

// ---------------------------------------------------------------------------
// Decode kernel (dominant): per t, per node n (16), per decode (recon/pred):
//   feat[32] = interleaved C-gated latents; h = relu(feat @ w0 + b0);
//   out = relu(h . w12 + beff)
// Lane-per-t; all layer0 weights for all 16 nodes in smem (broadcast reads);
// recon & pred share every weight load; packed f32x2 FMAs; 4 ILP chains.
// ---------------------------------------------------------------------------
#define DEC_BLOCK 288
#define DEC_GRID  456   // 456*288 = 131328 >= T_LEN, exactly 3 waves on 152 SMs
#define DEC_SMEM_FLOATS (D_X * 64 * 32 + D_X * 64 + D_X * 64 + 16)
#define DEC_SMEM_BYTES  (DEC_SMEM_FLOATS * 4)

__global__ __launch_bounds__(DEC_BLOCK, 1)
void decode_kernel(const float* __restrict__ lm, const float* __restrict__ lv,
                   const float* __restrict__ lb0, float* __restrict__ out) {
    extern __shared__ __align__(16) float smem[];
    float* sw0 = smem;                         // 32768
    float* sw12 = sw0 + D_X * 64 * 32;         // 1024
    float* sb0 = sw12 + D_X * 64;              // 1024
    float* sbeff = sb0 + D_X * 64;             // 16

    for (int i = threadIdx.x; i < (D_X * 64 * 32) / 4; i += blockDim.x)
        ((float4*)sw0)[i] = ((const float4*)g_w0t)[i];
    for (int i = threadIdx.x; i < D_X * 64; i += blockDim.x) {
        sw12[i] = g_w12[i];
        sb0[i] = lb0[i];
    }
    if (threadIdx.x < 16) sbeff[threadIdx.x] = g_beff[threadIdx.x];
    __syncthreads();

    int t = blockIdx.x * blockDim.x + threadIdx.x;
    if (t >= T_LEN) return;

    const float4* lm4 = (const float4*)lm;  // [2][T][8] -> 2 float4 per row
    const float4* lv4 = (const float4*)lv;
    float m0[8], m1[8], v0[8], v1[8];
    float pm0[8], pm1[8], pv0[8], pv1[8];
    *(float4*)&m0[0] = lm4[t * 2];
    *(float4*)&m0[4] = lm4[t * 2 + 1];
    *(float4*)&m1[0] = lm4[(T_LEN + t) * 2];
    *(float4*)&m1[4] = lm4[(T_LEN + t) * 2 + 1];
    *(float4*)&v0[0] = lv4[t * 2];
    *(float4*)&v0[4] = lv4[t * 2 + 1];
    *(float4*)&v1[0] = lv4[(T_LEN + t) * 2];
    *(float4*)&v1[4] = lv4[(T_LEN + t) * 2 + 1];
    float4 z = make_float4(0.f, 0.f, 0.f, 0.f);
    if (t > 0) {
        *(float4*)&pm0[0] = lm4[(t - 1) * 2];
        *(float4*)&pm0[4] = lm4[(t - 1) * 2 + 1];
        *(float4*)&pm1[0] = lm4[(T_LEN + t - 1) * 2];
        *(float4*)&pm1[4] = lm4[(T_LEN + t - 1) * 2 + 1];
        *(float4*)&pv0[0] = lv4[(t - 1) * 2];
        *(float4*)&pv0[4] = lv4[(t - 1) * 2 + 1];
        *(float4*)&pv1[0] = lv4[(T_LEN + t - 1) * 2];
        *(float4*)&pv1[4] = lv4[(T_LEN + t - 1) * 2 + 1];
    } else {
        *(float4*)&pm0[0] = z; *(float4*)&pm0[4] = z;
        *(float4*)&pm1[0] = z; *(float4*)&pm1[4] = z;
        *(float4*)&pv0[0] = z; *(float4*)&pv0[4] = z;
        *(float4*)&pv1[0] = z; *(float4*)&pv1[4] = z;
    }

    const float* ct = out + OFF_CT + t * 128;
    const float* ct1 = out + OFF_CT1 + t * 128;
    const float2 zz = make_float2(0.f, 0.f);

    for (int n = 0; n < D_X; n++) {
        float c[8], cp[8];
        *(float4*)&c[0] = *(const float4*)&ct[n * 8];
        *(float4*)&c[4] = *(const float4*)&ct[n * 8 + 4];
        *(float4*)&cp[0] = *(const float4*)&ct1[n * 8];
        *(float4*)&cp[4] = *(const float4*)&ct1[n * 8 + 4];

        float2 fR[16], fP[16];
#pragma unroll
        for (int k = 0; k < 8; k++) {
            fR[k]     = make_float2(c[k] * m0[k],  c[k] * m1[k]);
            fR[8 + k] = make_float2(c[k] * v0[k],  c[k] * v1[k]);
            fP[k]     = make_float2(cp[k] * pm0[k], cp[k] * pm1[k]);
            fP[8 + k] = make_float2(cp[k] * pv0[k], cp[k] * pv1[k]);
        }

        float outR = 0.f, outP = 0.f;
        const float4* w4base = (const float4*)&sw0[n * 2048];
        const float* b0n = &sb0[n * 64];
        const float* w12n = &sw12[n * 64];
#pragma unroll 2
        for (int j = 0; j < 64; j++) {
            const float4* w4 = w4base + j * 8;
            float2 aR0 = zz, aR1 = zz, aP0 = zz, aP1 = zz;
#pragma unroll
            for (int q = 0; q < 8; q += 2) {
                float4 wA = w4[q];
                float4 wB = w4[q + 1];
                float2 wa0 = make_float2(wA.x, wA.y), wa1 = make_float2(wA.z, wA.w);
                float2 wb0 = make_float2(wB.x, wB.y), wb1 = make_float2(wB.z, wB.w);
                aR0 = ffma2(fR[2 * q],     wa0, aR0);
                aR1 = ffma2(fR[2 * q + 1], wa1, aR1);
                aP0 = ffma2(fP[2 * q],     wa0, aP0);
                aP1 = ffma2(fP[2 * q + 1], wa1, aP1);
                aR0 = ffma2(fR[2 * q + 2], wb0, aR0);
                aR1 = ffma2(fR[2 * q + 3], wb1, aR1);
                aP0 = ffma2(fP[2 * q + 2], wb0, aP0);
                aP1 = ffma2(fP[2 * q + 3], wb1, aP1);
            }
            float b = b0n[j];
            float wv = w12n[j];
            float hR = fmaxf(aR0.x + aR0.y + aR1.x + aR1.y + b, 0.f);
            float hP = fmaxf(aP0.x + aP0.y + aP1.x + aP1.y + b, 0.f);
            outR = fmaf(hR, wv, outR);
            outP = fmaf(hP, wv, outP);
        }
        float be = sbeff[n];
        out[OFF_RECON + t * 16 + n] = fmaxf(outR + be, 0.f);
        out[OFF_PRED + t * 16 + n] = fmaxf(outP + be, 0.f);
    }
}

// ---------------------------------------------------------------------------
extern "C" void kernel_launch(void* const* d_in, const int* in_sizes, int n_in,
                              void* d_out, int out_size) {
    const float* lm  = (const float*)d_in[0];
    const float* lv  = (const float*)d_in[1];
    const float* Tin = (const float*)d_in[2];
    const float* cw0 = (const float*)d_in[3];
    const float* cb0 = (const float*)d_in[4];
    const float* cw1 = (const float*)d_in[5];
    const float* cb1 = (const float*)d_in[6];
    const float* cw2 = (const float*)d_in[7];
    const float* cb2 = (const float*)d_in[8];
    const float* pw0 = (const float*)d_in[9];
    const float* pb0 = (const float*)d_in[10];
    const float* pw1 = (const float*)d_in[11];
    const float* pb1 = (const float*)d_in[12];
    const float* pw2 = (const float*)d_in[13];
    const float* pb2 = (const float*)d_in[14];
    const float* fmw1 = (const float*)d_in[15];
    const float* fmb1 = (const float*)d_in[16];
    const float* fmw2 = (const float*)d_in[17];
    const float* fmb2 = (const float*)d_in[18];
    const float* fvw1 = (const float*)d_in[19];
    const float* fvb1 = (const float*)d_in[20];
    const float* fvw2 = (const float*)d_in[21];
    const float* fvb2 = (const float*)d_in[22];
    const float* lw0 = (const float*)d_in[23];
    const float* lb0 = (const float*)d_in[24];
    const float* lw1 = (const float*)d_in[25];
    const float* lb1 = (const float*)d_in[26];
    const float* lw2 = (const float*)d_in[27];
    const float* lb2 = (const float*)d_in[28];
    float* out = (float*)d_out;

    cudaFuncSetAttribute(decode_kernel, cudaFuncAttributeMaxDynamicSharedMemorySize,
                         DEC_SMEM_BYTES);

    prep_kernel<<<1, 1024>>>(lw0, lw1, lw2, lb1, lb2);
    enc_kernel<<<T_LEN / 256, 256>>>(Tin, cw0, cb0, cw1, cb1, cw2, cb2,
                                     pw0, pb0, pw1, pb1, pw2, pb2, out);
    head_kernel<<<(2 * T_LEN) / 256, 256>>>(lm, lv, fmw1, fmb1, fmw2, fmb2,
                                            fvw1, fvb1, fvw2, fvb2, out);
    decode_kernel<<<DEC_GRID, DEC_BLOCK, DEC_SMEM_BYTES>>>(lm, lv, lb0, out);
}

// round 2
// speedup vs baseline: 1.1322x; 1.1322x over previous
#include <cuda_runtime.h>
#include <cstdint>

#define T_LEN 131072
#define D_X 16
#define D_L 8

// d_out layout (flat concat of reference tuple, all float32)
#define OFF_RECON 0
#define OFF_PRED  (T_LEN * D_X)
#define OFF_LMP   (2 * T_LEN * D_X)
#define OFF_LVP   (OFF_LMP + 2 * T_LEN * D_L)
#define OFF_CT    (OFF_LVP + 2 * T_LEN * D_L)
#define OFF_CT1   (OFF_CT + T_LEN * D_X * D_L)

// ---------------------------------------------------------------------------
// Packed fp32x2 ops (Blackwell)
// ---------------------------------------------------------------------------
__device__ __forceinline__ float2 ffma2(float2 a, float2 b, float2 c) {
    float2 d;
    asm("{\n\t"
        ".reg .b64 ra, rb, rc, rd;\n\t"
        "mov.b64 ra, {%2, %3};\n\t"
        "mov.b64 rb, {%4, %5};\n\t"
        "mov.b64 rc, {%6, %7};\n\t"
        "fma.rn.f32x2 rd, ra, rb, rc;\n\t"
        "mov.b64 {%0, %1}, rd;\n\t"
        "}"
        : "=f"(d.x), "=f"(d.y)
        : "f"(a.x), "f"(a.y), "f"(b.x), "f"(b.y), "f"(c.x), "f"(c.y));
    return d;
}
__device__ __forceinline__ float2 fadd2(float2 a, float2 b) {
    float2 d;
    asm("{\n\t"
        ".reg .b64 ra, rb, rd;\n\t"
        "mov.b64 ra, {%2, %3};\n\t"
        "mov.b64 rb, {%4, %5};\n\t"
        "add.rn.f32x2 rd, ra, rb;\n\t"
        "mov.b64 {%0, %1}, rd;\n\t"
        "}"
        : "=f"(d.x), "=f"(d.y)
        : "f"(a.x), "f"(a.y), "f"(b.x), "f"(b.y));
    return d;
}

// ---------------------------------------------------------------------------
// Preprocessed decoder weights (device-global scratch; no allocation).
// ---------------------------------------------------------------------------
__device__ __align__(16) float g_w0t[D_X * 64 * 32];  // [n][j][f]
__device__ __align__(16) float g_w12[D_X * 64];       // collapsed lw1@lw2
__device__ __align__(16) float g_beff[D_X];           // lb1@lw2 + lb2

__global__ void prep_kernel(const float* __restrict__ lw0,
                            const float* __restrict__ lw1,
                            const float* __restrict__ lw2,
                            const float* __restrict__ lb0,
                            const float* __restrict__ lb1,
                            const float* __restrict__ lb2,
                            float* __restrict__ out) {
    int tid = threadIdx.x;          // 1024 threads: (n, j)
    int n = tid >> 6;
    int j = tid & 63;
#pragma unroll
    for (int f = 0; f < 32; f++)
        g_w0t[(n * 64 + j) * 32 + f] = lw0[(n * 32 + f) * 64 + j];
    float acc = 0.f;
#pragma unroll 8
    for (int o = 0; o < 64; o++)
        acc = fmaf(lw1[(n * 64 + j) * 64 + o], lw2[n * 64 + o], acc);
    g_w12[n * 64 + j] = acc;
    if (j == 0) {
        float b = lb2[n];
        for (int o = 0; o < 64; o++)
            b = fmaf(lb1[n * 64 + o], lw2[n * 64 + o], b);
        g_beff[n] = b;
    }
    __syncthreads();
    // pred[0]: features are all-zero -> h = relu(lb0), out = relu(h.w12 + beff)
    if (j == 0) {
        float s = g_beff[n];
        for (int o = 0; o < 64; o++) {
            float h = fmaxf(lb0[n * 64 + o], 0.f);
            s = fmaf(h, g_w12[n * 64 + o], s);
        }
        out[OFF_PRED + n] = fmaxf(s, 0.f);
    }
}

// ---------------------------------------------------------------------------
// Encoder branch layouts in smem: w0[8] b0[8] w1[64] b1[8] w2[1024] b2[128]
// ---------------------------------------------------------------------------
#define EW0 0
#define EB0 8
#define EW1 16
#define EB1 80
#define EW2 88
#define EB2 1112
#define ESZ 1240

// layers 0+1 only -> h1[8]
__device__ __forceinline__ void enc01(float s, const float* __restrict__ w,
                                      float* __restrict__ h1) {
    float h0[8];
#pragma unroll
    for (int i = 0; i < 8; i++) {
        float v = fmaf(s, w[EW0 + i], w[EB0 + i]);
        h0[i] = v > 0.f ? v : 0.01f * v;
    }
#pragma unroll
    for (int j = 0; j < 8; j++) {
        float a = 0.f;
#pragma unroll
        for (int i = 0; i < 8; i++) a = fmaf(h0[i], w[EW1 + i * 8 + j], a);
        a += w[EB1 + j];
        h1[j] = a > 0.f ? a : 0.01f * a;
    }
}

// full branch, continuous output written to dst
__device__ __forceinline__ void enc_full_cont(float s, const float* __restrict__ w,
                                              float* __restrict__ dst) {
    float h1[8];
    enc01(s, w, h1);
#pragma unroll 4
    for (int m = 0; m < 128; m += 4) {
        float4 a = make_float4(0.f, 0.f, 0.f, 0.f);
#pragma unroll
        for (int j = 0; j < 8; j++) {
            float4 ww = *(const float4*)&w[EW2 + j * 128 + m];
            a.x = fmaf(h1[j], ww.x, a.x);
            a.y = fmaf(h1[j], ww.y, a.y);
            a.z = fmaf(h1[j], ww.z, a.z);
            a.w = fmaf(h1[j], ww.w, a.w);
        }
        a.x += w[EB2 + m + 0];
        a.y += w[EB2 + m + 1];
        a.z += w[EB2 + m + 2];
        a.w += w[EB2 + m + 3];
        *(float4*)&dst[m] = a;
    }
}

// full branch, binarized output written to dst, bitmask returned (bit set if >= 0.1)
__device__ __forceinline__ void enc_full_bin(float s, const float* __restrict__ w,
                                             float* __restrict__ dst,
                                             unsigned* __restrict__ mask) {
    float h1[8];
    enc01(s, w, h1);
    mask[0] = mask[1] = mask[2] = mask[3] = 0u;
#pragma unroll 4
    for (int m = 0; m < 128; m += 4) {
        float4 a = make_float4(0.f, 0.f, 0.f, 0.f);
#pragma unroll
        for (int j = 0; j < 8; j++) {
            float4 ww = *(const float4*)&w[EW2 + j * 128 + m];
            a.x = fmaf(h1[j], ww.x, a.x);
            a.y = fmaf(h1[j], ww.y, a.y);
            a.z = fmaf(h1[j], ww.z, a.z);
            a.w = fmaf(h1[j], ww.w, a.w);
        }
        a.x += w[EB2 + m + 0];
        a.y += w[EB2 + m + 1];
        a.z += w[EB2 + m + 2];
        a.w += w[EB2 + m + 3];
        unsigned wi = m >> 5;
        unsigned bit = m & 31;
        unsigned mm = mask[wi];
        float4 o;
        if (a.x < 0.1f) { o.x = 0.f; } else { o.x = 1.f; mm |= 1u << (bit + 0); }
        if (a.y < 0.1f) { o.y = 0.f; } else { o.y = 1.f; mm |= 1u << (bit + 1); }
        if (a.z < 0.1f) { o.z = 0.f; } else { o.z = 1.f; mm |= 1u << (bit + 2); }
        if (a.w < 0.1f) { o.w = 0.f; } else { o.w = 1.f; mm |= 1u << (bit + 3); }
        mask[wi] = mm;
        *(float4*)&dst[m] = o;
    }
}

// ---------------------------------------------------------------------------
// Head: relu(x @ W1 + b1) @ W2 + b2   (8->128->8), one row
// ---------------------------------------------------------------------------
__device__ __forceinline__ void head_fn(const float* __restrict__ x8,
                                        const float* __restrict__ w1t,  // [j][k]
                                        const float* __restrict__ b1,
                                        const float* __restrict__ w2,   // [j][o]
                                        const float* __restrict__ b2,
                                        float* __restrict__ dst) {
    float4 xa = *(const float4*)&x8[0];
    float4 xb = *(const float4*)&x8[4];
    float2 xx0 = make_float2(xa.x, xa.y), xx1 = make_float2(xa.z, xa.w);
    float2 xx2 = make_float2(xb.x, xb.y), xx3 = make_float2(xb.z, xb.w);
    float4 b2a = *(const float4*)&b2[0];
    float4 b2b = *(const float4*)&b2[4];
    float2 o0 = make_float2(b2a.x, b2a.y), o1 = make_float2(b2a.z, b2a.w);
    float2 o2 = make_float2(b2b.x, b2b.y), o3 = make_float2(b2b.z, b2b.w);
    const float2 zz = make_float2(0.f, 0.f);
#pragma unroll 4
    for (int j = 0; j < 128; j++) {
        float4 wA = *(const float4*)&w1t[j * 8];
        float4 wB = *(const float4*)&w1t[j * 8 + 4];
        float2 a0 = ffma2(xx0, make_float2(wA.x, wA.y), zz);
        float2 a1 = ffma2(xx2, make_float2(wB.x, wB.y), zz);
        a0 = ffma2(xx1, make_float2(wA.z, wA.w), a0);
        a1 = ffma2(xx3, make_float2(wB.z, wB.w), a1);
        float h = a0.x + a0.y + a1.x + a1.y + b1[j];
        h = fmaxf(h, 0.f);
        float2 hh = make_float2(h, h);
        float4 u = *(const float4*)&w2[j * 8];
        float4 v = *(const float4*)&w2[j * 8 + 4];
        o0 = ffma2(hh, make_float2(u.x, u.y), o0);
        o1 = ffma2(hh, make_float2(u.z, u.w), o1);
        o2 = ffma2(hh, make_float2(v.x, v.y), o2);
        o3 = ffma2(hh, make_float2(v.z, v.w), o3);
    }
    *(float4*)&dst[0] = make_float4(o0.x, o0.y, o1.x, o1.y);
    *(float4*)&dst[4] = make_float4(o2.x, o2.y, o3.x, o3.y);
}

// ---------------------------------------------------------------------------
// Mega kernel: enc + head + both decodes, one thread per timestep t.
// Thread t computes recon(t) and pred(t+1)  (pred(0) done by prep_kernel).
// ---------------------------------------------------------------------------
#define MB 448
#define MGRID ((T_LEN + MB - 1) / MB)   // 293 -> 2 waves on 152 SMs

// smem float offsets
#define S_W0   0
#define S_BW   32768
#define S_BEFF 34816
#define S_EC   34832
#define S_EP   (S_EC + ESZ)
#define S_MW1T (S_EP + ESZ)
#define S_MW2  (S_MW1T + 1024)
#define S_MB1  (S_MW2 + 1024)
#define S_MB2  (S_MB1 + 128)
#define S_VW1T (S_MB2 + 8)
#define S_VW2  (S_VW1T + 1024)
#define S_VB1  (S_VW2 + 1024)
#define S_VB2  (S_VB1 + 128)
#define S_TOT  (S_VB2 + 8)
#define MEGA_SMEM_BYTES (S_TOT * 4)

__global__ __launch_bounds__(MB, 1)
void mega_kernel(const float* __restrict__ lm, const float* __restrict__ lv,
                 const float* __restrict__ Tin,
                 const float* cw0, const float* cb0, const float* cw1,
                 const float* cb1, const float* cw2, const float* cb2,
                 const float* pw0, const float* pb0, const float* pw1,
                 const float* pb1, const float* pw2, const float* pb2,
                 const float* fmw1, const float* fmb1,
                 const float* fmw2, const float* fmb2,
                 const float* fvw1, const float* fvb1,
                 const float* fvw2, const float* fvb2,
                 const float* __restrict__ lb0,
                 float* __restrict__ out) {
    extern __shared__ __align__(16) float smem[];
    int tid = threadIdx.x;

    // ---- cooperative smem fill ----
    for (int i = tid; i < (D_X * 64 * 32) / 4; i += MB)
        ((float4*)(smem + S_W0))[i] = ((const float4*)g_w0t)[i];
    for (int i = tid; i < D_X * 64; i += MB) {
        smem[S_BW + 2 * i]     = lb0[i];
        smem[S_BW + 2 * i + 1] = g_w12[i];
    }
    if (tid < 16) smem[S_BEFF + tid] = g_beff[tid];
    for (int i = tid; i < ESZ; i += MB) {
        float v, u;
        if (i < 8)         { v = cw0[i];        u = pw0[i];        }
        else if (i < 16)   { v = cb0[i - 8];    u = pb0[i - 8];    }
        else if (i < 80)   { v = cw1[i - 16];   u = pw1[i - 16];   }
        else if (i < 88)   { v = cb1[i - 80];   u = pb1[i - 80];   }
        else if (i < 1112) { v = cw2[i - 88];   u = pw2[i - 88];   }
        else               { v = cb2[i - 1112]; u = pb2[i - 1112]; }
        smem[S_EC + i] = v;
        smem[S_EP + i] = u;
    }
    for (int i = tid; i < 1024; i += MB) {
        int j = i >> 3, k = i & 7;
        smem[S_MW1T + i] = fmw1[k * 128 + j];
        smem[S_VW1T + i] = fvw1[k * 128 + j];
        smem[S_MW2 + i] = fmw2[i];
        smem[S_VW2 + i] = fvw2[i];
    }
    if (tid < 128) { smem[S_MB1 + tid] = fmb1[tid]; smem[S_VB1 + tid] = fvb1[tid]; }
    if (tid < 8)   { smem[S_MB2 + tid] = fmb2[tid]; smem[S_VB2 + tid] = fvb2[tid]; }
    __syncthreads();

    int t = blockIdx.x * MB + tid;
    if (t >= T_LEN) return;

    // ---- enc phase ----
    unsigned mask[4];
    float s = Tin[t];
    enc_full_bin(s, smem + S_EC, out + OFF_CT + (size_t)t * 128, mask);
    enc_full_cont(s, smem + S_EP, out + OFF_CT1 + (size_t)t * 128);
    bool hasP = (t + 1 < T_LEN);
    float h1p[8];
    {
        float s2 = hasP ? Tin[t + 1] : 0.f;
        enc01(s2, smem + S_EP, h1p);
    }

    // ---- head phase (rows t and T+t for both heads) ----
    head_fn(lm + (size_t)t * 8, smem + S_MW1T, smem + S_MB1, smem + S_MW2,
            smem + S_MB2, out + OFF_LMP + (size_t)t * 8);
    head_fn(lm + ((size_t)T_LEN + t) * 8, smem + S_MW1T, smem + S_MB1,
            smem + S_MW2, smem + S_MB2, out + OFF_LMP + ((size_t)T_LEN + t) * 8);
    head_fn(lv + (size_t)t * 8, smem + S_VW1T, smem + S_VB1, smem + S_VW2,
            smem + S_VB2, out + OFF_LVP + (size_t)t * 8);
    head_fn(lv + ((size_t)T_LEN + t) * 8, smem + S_VW1T, smem + S_VB1,
            smem + S_VW2, smem + S_VB2, out + OFF_LVP + ((size_t)T_LEN + t) * 8);

    // ---- decode phase ----
    // M[k] = (lm[0,t,k], lm[1,t,k]); V[k] = (lv[0,t,k], lv[1,t,k])
    const float4* lm4 = (const float4*)lm;
    const float4* lv4 = (const float4*)lv;
    float4 a0 = lm4[(size_t)t * 2], a1 = lm4[(size_t)t * 2 + 1];
    float4 b0 = lm4[((size_t)T_LEN + t) * 2], b1 = lm4[((size_t)T_LEN + t) * 2 + 1];
    float4 c0 = lv4[(size_t)t * 2], c1 = lv4[(size_t)t * 2 + 1];
    float4 d0 = lv4[((size_t)T_LEN + t) * 2], d1 = lv4[((size_t)T_LEN + t) * 2 + 1];
    float2 M[8], V[8];
    M[0] = make_float2(a0.x, b0.x); M[1] = make_float2(a0.y, b0.y);
    M[2] = make_float2(a0.z, b0.z); M[3] = make_float2(a0.w, b0.w);
    M[4] = make_float2(a1.x, b1.x); M[5] = make_float2(a1.y, b1.y);
    M[6] = make_float2(a1.z, b1.z); M[7] = make_float2(a1.w, b1.w);
    V[0] = make_float2(c0.x, d0.x); V[1] = make_float2(c0.y, d0.y);
    V[2] = make_float2(c0.z, d0.z); V[3] = make_float2(c0.w, d0.w);
    V[4] = make_float2(c1.x, d1.x); V[5] = make_float2(c1.y, d1.y);
    V[6] = make_float2(c1.z, d1.z); V[7] = make_float2(c1.w, d1.w);

    const float2 zz = make_float2(0.f, 0.f);
    float reconOut, predOut;

    for (int n = 0; n < D_X; n++) {
        unsigned byte = (mask[n >> 2] >> ((n & 3) * 8)) & 0xffu;

        float2 fR[16], fP[16];
#pragma unroll
        for (int k = 0; k < 8; k++) {
            bool on = (byte >> k) & 1u;
            fR[k]     = on ? M[k] : zz;
            fR[8 + k] = on ? V[k] : zz;
        }
        // cp[k] = pre-enc layer2 output at (t+1) for features n*8+k (recomputed)
#pragma unroll
        for (int k = 0; k < 8; k++) {
            const float* w2p = smem + S_EP + EW2 + n * 8 + k;
            float cp = 0.f;
#pragma unroll
            for (int i = 0; i < 8; i++) cp = fmaf(h1p[i], w2p[i * 128], cp);
            cp += smem[S_EP + EB2 + n * 8 + k];
            fP[k]     = make_float2(cp * M[k].x, cp * M[k].y);
            fP[8 + k] = make_float2(cp * V[k].x, cp * V[k].y);
        }

        float outR = 0.f, outP = 0.f;
        const float4* w4base = (const float4*)(smem + S_W0 + n * 2048);
        const float2* bw = (const float2*)(smem + S_BW + 2 * n * 64);
#pragma unroll 2
        for (int j = 0; j < 64; j++) {
            const float4* w4 = w4base + j * 8;
            float2 aR0 = zz, aR1 = zz, aP0 = zz, aP1 = zz;
#pragma unroll
            for (int q = 0; q < 8; q++) {
                float4 wA = w4[q];
                float2 w0p = make_float2(wA.x, wA.y);
                float2 w1p = make_float2(wA.z, wA.w);
                aR0 = ffma2(fR[2 * q],     w0p, aR0);
                aR1 = ffma2(fR[2 * q + 1], w1p, aR1);
                aP0 = ffma2(fP[2 * q],     w0p, aP0);
                aP1 = ffma2(fP[2 * q + 1], w1p, aP1);
            }
            float2 bwj = bw[j];
            float2 sR = fadd2(aR0, aR1);
            float2 sP = fadd2(aP0, aP1);
            float hR = fmaxf(sR.x + sR.y + bwj.x, 0.f);
            float hP = fmaxf(sP.x + sP.y + bwj.x, 0.f);
            outR = fmaf(hR, bwj.y, outR);
            outP = fmaf(hP, bwj.y, outP);
        }
        float be = smem[S_BEFF + n];
        reconOut = fmaxf(outR + be, 0.f);
        predOut = fmaxf(outP + be, 0.f);
        out[OFF_RECON + (size_t)t * 16 + n] = reconOut;
        if (hasP) out[OFF_PRED + (size_t)(t + 1) * 16 + n] = predOut;
    }
}

// ---------------------------------------------------------------------------
extern "C" void kernel_launch(void* const* d_in, const int* in_sizes, int n_in,
                              void* d_out, int out_size) {
    const float* lm  = (const float*)d_in[0];
    const float* lv  = (const float*)d_in[1];
    const float* Tin = (const float*)d_in[2];
    const float* cw0 = (const float*)d_in[3];
    const float* cb0 = (const float*)d_in[4];
    const float* cw1 = (const float*)d_in[5];
    const float* cb1 = (const float*)d_in[6];
    const float* cw2 = (const float*)d_in[7];
    const float* cb2 = (const float*)d_in[8];
    const float* pw0 = (const float*)d_in[9];
    const float* pb0 = (const float*)d_in[10];
    const float* pw1 = (const float*)d_in[11];
    const float* pb1 = (const float*)d_in[12];
    const float* pw2 = (const float*)d_in[13];
    const float* pb2 = (const float*)d_in[14];
    const float* fmw1 = (const float*)d_in[15];
    const float* fmb1 = (const float*)d_in[16];
    const float* fmw2 = (const float*)d_in[17];
    const float* fmb2 = (const float*)d_in[18];
    const float* fvw1 = (const float*)d_in[19];
    const float* fvb1 = (const float*)d_in[20];
    const float* fvw2 = (const float*)d_in[21];
    const float* fvb2 = (const float*)d_in[22];
    const float* lw0 = (const float*)d_in[23];
    const float* lb0 = (const float*)d_in[24];
    const float* lw1 = (const float*)d_in[25];
    const float* lb1 = (const float*)d_in[26];
    const float* lw2 = (const float*)d_in[27];
    const float* lb2 = (const float*)d_in[28];
    float* out = (float*)d_out;

    cudaFuncSetAttribute(mega_kernel, cudaFuncAttributeMaxDynamicSharedMemorySize,
                         MEGA_SMEM_BYTES);

    prep_kernel<<<1, 1024>>>(lw0, lw1, lw2, lb0, lb1, lb2, out);
    mega_kernel<<<MGRID, MB, MEGA_SMEM_BYTES>>>(
        lm, lv, Tin,
        cw0, cb0, cw1, cb1, cw2, cb2,
        pw0, pb0, pw1, pb1, pw2, pb2,
        fmw1, fmb1, fmw2, fmb2,
        fvw1, fvb1, fvw2, fvb2,
        lb0, out);
}

// round 3
// speedup vs baseline: 1.1960x; 1.0563x over previous
#include <cuda_runtime.h>
#include <cstdint>

#define T_LEN 131072
#define D_X 16
#define D_L 8

// d_out layout (flat concat of reference tuple, all float32)
#define OFF_RECON 0
#define OFF_PRED  (T_LEN * D_X)
#define OFF_LMP   (2 * T_LEN * D_X)
#define OFF_LVP   (OFF_LMP + 2 * T_LEN * D_L)
#define OFF_CT    (OFF_LVP + 2 * T_LEN * D_L)
#define OFF_CT1   (OFF_CT + T_LEN * D_X * D_L)

// ---------------------------------------------------------------------------
// Packed fp32x2 ops (Blackwell)
// ---------------------------------------------------------------------------
__device__ __forceinline__ float2 ffma2(float2 a, float2 b, float2 c) {
    float2 d;
    asm("{\n\t"
        ".reg .b64 ra, rb, rc, rd;\n\t"
        "mov.b64 ra, {%2, %3};\n\t"
        "mov.b64 rb, {%4, %5};\n\t"
        "mov.b64 rc, {%6, %7};\n\t"
        "fma.rn.f32x2 rd, ra, rb, rc;\n\t"
        "mov.b64 {%0, %1}, rd;\n\t"
        "}"
        : "=f"(d.x), "=f"(d.y)
        : "f"(a.x), "f"(a.y), "f"(b.x), "f"(b.y), "f"(c.x), "f"(c.y));
    return d;
}
__device__ __forceinline__ float2 fadd2(float2 a, float2 b) {
    float2 d;
    asm("{\n\t"
        ".reg .b64 ra, rb, rd;\n\t"
        "mov.b64 ra, {%2, %3};\n\t"
        "mov.b64 rb, {%4, %5};\n\t"
        "add.rn.f32x2 rd, ra, rb;\n\t"
        "mov.b64 {%0, %1}, rd;\n\t"
        "}"
        : "=f"(d.x), "=f"(d.y)
        : "f"(a.x), "f"(a.y), "f"(b.x), "f"(b.y));
    return d;
}
__device__ __forceinline__ float2 fmul2(float2 a, float2 b) {
    float2 d;
    asm("{\n\t"
        ".reg .b64 ra, rb, rd;\n\t"
        "mov.b64 ra, {%2, %3};\n\t"
        "mov.b64 rb, {%4, %5};\n\t"
        "mul.rn.f32x2 rd, ra, rb;\n\t"
        "mov.b64 {%0, %1}, rd;\n\t"
        "}"
        : "=f"(d.x), "=f"(d.y)
        : "f"(a.x), "f"(a.y), "f"(b.x), "f"(b.y));
    return d;
}

// ---------------------------------------------------------------------------
// Preprocessed decoder weights (device-global scratch; no allocation).
// ---------------------------------------------------------------------------
__device__ __align__(16) float g_w0t[D_X * 64 * 32];  // [n][j][f]
__device__ __align__(16) float g_w12[D_X * 64];       // collapsed lw1@lw2
__device__ __align__(16) float g_beff[D_X];           // lb1@lw2 + lb2

__global__ void prep_kernel(const float* __restrict__ lw0,
                            const float* __restrict__ lw1,
                            const float* __restrict__ lw2,
                            const float* __restrict__ lb0,
                            const float* __restrict__ lb1,
                            const float* __restrict__ lb2,
                            float* __restrict__ out) {
    int tid = threadIdx.x;          // 1024 threads: (n, j)
    int n = tid >> 6;
    int j = tid & 63;
#pragma unroll
    for (int f = 0; f < 32; f++)
        g_w0t[(n * 64 + j) * 32 + f] = lw0[(n * 32 + f) * 64 + j];
    float acc = 0.f;
#pragma unroll 8
    for (int o = 0; o < 64; o++)
        acc = fmaf(lw1[(n * 64 + j) * 64 + o], lw2[n * 64 + o], acc);
    g_w12[n * 64 + j] = acc;
    if (j == 0) {
        float b = lb2[n];
        for (int o = 0; o < 64; o++)
            b = fmaf(lb1[n * 64 + o], lw2[n * 64 + o], b);
        g_beff[n] = b;
    }
    __syncthreads();
    // pred[0]: features are all-zero -> h = relu(lb0), out = relu(h.w12 + beff)
    if (j == 0) {
        float s = g_beff[n];
        for (int o = 0; o < 64; o++) {
            float h = fmaxf(lb0[n * 64 + o], 0.f);
            s = fmaf(h, g_w12[n * 64 + o], s);
        }
        out[OFF_PRED + n] = fmaxf(s, 0.f);
    }
}

// ---------------------------------------------------------------------------
// enc layers 0+1 (packed block: w0[8] b0[8] w1[64] b1[8]) -> h1[8]
// ---------------------------------------------------------------------------
__device__ __forceinline__ void enc01(float s, const float* __restrict__ w,
                                      float* __restrict__ h1) {
    float h0[8];
#pragma unroll
    for (int i = 0; i < 8; i++) {
        float v = fmaf(s, w[i], w[8 + i]);
        h0[i] = v > 0.f ? v : 0.01f * v;
    }
#pragma unroll
    for (int j = 0; j < 8; j++) {
        float a = 0.f;
#pragma unroll
        for (int i = 0; i < 8; i++) a = fmaf(h0[i], w[16 + i * 8 + j], a);
        a += w[80 + j];
        h1[j] = a > 0.f ? a : 0.01f * a;
    }
}

// ---------------------------------------------------------------------------
// Head: relu(x @ W1 + b1) @ W2 + b2   (8->128->8), one row
// ---------------------------------------------------------------------------
__device__ __forceinline__ void head_fn(const float* __restrict__ x8,
                                        const float* __restrict__ w1t,  // [j][k]
                                        const float* __restrict__ b1,
                                        const float* __restrict__ w2,   // [j][o]
                                        const float* __restrict__ b2,
                                        float* __restrict__ dst) {
    float4 xa = *(const float4*)&x8[0];
    float4 xb = *(const float4*)&x8[4];
    float2 xx0 = make_float2(xa.x, xa.y), xx1 = make_float2(xa.z, xa.w);
    float2 xx2 = make_float2(xb.x, xb.y), xx3 = make_float2(xb.z, xb.w);
    float4 b2a = *(const float4*)&b2[0];
    float4 b2b = *(const float4*)&b2[4];
    float2 o0 = make_float2(b2a.x, b2a.y), o1 = make_float2(b2a.z, b2a.w);
    float2 o2 = make_float2(b2b.x, b2b.y), o3 = make_float2(b2b.z, b2b.w);
    const float2 zz = make_float2(0.f, 0.f);
#pragma unroll 4
    for (int j = 0; j < 128; j++) {
        float4 wA = *(const float4*)&w1t[j * 8];
        float4 wB = *(const float4*)&w1t[j * 8 + 4];
        float2 a0 = ffma2(xx0, make_float2(wA.x, wA.y), zz);
        float2 a1 = ffma2(xx2, make_float2(wB.x, wB.y), zz);
        a0 = ffma2(xx1, make_float2(wA.z, wA.w), a0);
        a1 = ffma2(xx3, make_float2(wB.z, wB.w), a1);
        float h = a0.x + a0.y + a1.x + a1.y + b1[j];
        h = fmaxf(h, 0.f);
        float2 hh = make_float2(h, h);
        float4 u = *(const float4*)&w2[j * 8];
        float4 v = *(const float4*)&w2[j * 8 + 4];
        o0 = ffma2(hh, make_float2(u.x, u.y), o0);
        o1 = ffma2(hh, make_float2(u.z, u.w), o1);
        o2 = ffma2(hh, make_float2(v.x, v.y), o2);
        o3 = ffma2(hh, make_float2(v.z, v.w), o3);
    }
    *(float4*)&dst[0] = make_float4(o0.x, o0.y, o1.x, o1.y);
    *(float4*)&dst[4] = make_float4(o2.x, o2.y, o3.x, o3.y);
}

// ---------------------------------------------------------------------------
// Mega kernel, node-split: blockIdx.y = half (nodes 8h..8h+7).
// Thread t computes recon(t) and pred(t+1) for its half's nodes.
// ---------------------------------------------------------------------------
#define HB 288
#define HGX 456   // 456*288 = 131328 >= T_LEN; 912 CTAs = 3 waves @ 2 CTA/SM

// smem float offsets
#define S_W0    0                    // 8*64*32 = 16384
#define S_BW    16384                // [ln][j] (b0, w12) pairs: 1024
#define S_BEFF  17408                // 8
#define S_CL01  17416                // 88
#define S_PL01  17504                // 88
#define S_CW2T  17592                // [ln][k][i] 512
#define S_CB2   18104                // 64
#define S_PW2T  18168                // 512
#define S_PB2   18680                // 64
#define S_HW1T  18744                // 1024
#define S_HB1   19768                // 128
#define S_HW2   19896                // 1024
#define S_HB2   20920                // 8
#define S_V     20928                // 16 * HB = 4608
#define S_TOT   (S_V + 16 * HB)      // 25536 floats
#define MEGA_SMEM_BYTES (S_TOT * 4)  // 102144 B

__global__ __launch_bounds__(HB, 2)
void mega_kernel(const float* __restrict__ lm, const float* __restrict__ lv,
                 const float* __restrict__ Tin,
                 const float* cw0, const float* cb0, const float* cw1,
                 const float* cb1, const float* cw2, const float* cb2,
                 const float* pw0, const float* pb0, const float* pw1,
                 const float* pb1, const float* pw2, const float* pb2,
                 const float* fmw1, const float* fmb1,
                 const float* fmw2, const float* fmb2,
                 const float* fvw1, const float* fvb1,
                 const float* fvw2, const float* fvb2,
                 const float* __restrict__ lb0,
                 float* __restrict__ out) {
    extern __shared__ __align__(16) float smem[];
    const int tid = threadIdx.x;
    const int half = blockIdx.y;
    const int nb = half * 8;          // node base

    // ---- cooperative smem fill ----
    for (int i = tid; i < (8 * 64 * 32) / 4; i += HB)
        ((float4*)(smem + S_W0))[i] = ((const float4*)(g_w0t + nb * 2048))[i];
    for (int i = tid; i < 512; i += HB) {
        smem[S_BW + 2 * i]     = lb0[nb * 64 + i];
        smem[S_BW + 2 * i + 1] = g_w12[nb * 64 + i];
    }
    if (tid < 8) smem[S_BEFF + tid] = g_beff[nb + tid];
    for (int i = tid; i < 88; i += HB) {
        float v, u;
        if (i < 8)       { v = cw0[i];      u = pw0[i];      }
        else if (i < 16) { v = cb0[i - 8];  u = pb0[i - 8];  }
        else if (i < 80) { v = cw1[i - 16]; u = pw1[i - 16]; }
        else             { v = cb1[i - 80]; u = pb1[i - 80]; }
        smem[S_CL01 + i] = v;
        smem[S_PL01 + i] = u;
    }
    for (int i = tid; i < 512; i += HB) {
        int ln = i >> 6, k = (i >> 3) & 7, ii = i & 7;
        int src = ii * 128 + nb * 8 + ln * 8 + k;
        smem[S_CW2T + i] = cw2[src];
        smem[S_PW2T + i] = pw2[src];
    }
    for (int i = tid; i < 64; i += HB) {
        smem[S_CB2 + i] = cb2[nb * 8 + i];
        smem[S_PB2 + i] = pb2[nb * 8 + i];
    }
    {
        const float* hw1 = half ? fvw1 : fmw1;
        const float* hw2 = half ? fvw2 : fmw2;
        const float* hb1 = half ? fvb1 : fmb1;
        const float* hb2 = half ? fvb2 : fmb2;
        for (int i = tid; i < 1024; i += HB) {
            int j = i >> 3, k = i & 7;
            smem[S_HW1T + i] = hw1[k * 128 + j];
            smem[S_HW2 + i]  = hw2[i];
        }
        if (tid < 128) smem[S_HB1 + tid] = hb1[tid];
        if (tid < 8)   smem[S_HB2 + tid] = hb2[tid];
    }
    __syncthreads();

    const int t = blockIdx.x * HB + tid;
    if (t >= T_LEN) return;

    // ---- enc phase ----
    float s = Tin[t];
    unsigned mbytes0 = 0, mbytes1 = 0;   // 8 bytes of per-node masks
    {
        float h1c[8];
        enc01(s, smem + S_CL01, h1c);
        float* ctdst = out + OFF_CT + (size_t)t * 128 + nb * 8;
#pragma unroll
        for (int ln = 0; ln < 8; ln++) {
            float vals[8];
#pragma unroll
            for (int k = 0; k < 8; k++) {
                const float* w = smem + S_CW2T + (ln * 8 + k) * 8;
                float a = 0.f;
#pragma unroll
                for (int i = 0; i < 8; i++) a = fmaf(h1c[i], w[i], a);
                a += smem[S_CB2 + ln * 8 + k];
                bool on = !(a < 0.1f);
                vals[k] = on ? 1.f : 0.f;
                if (on) {
                    if (ln < 4) mbytes0 |= 1u << ((ln & 3) * 8 + k);
                    else        mbytes1 |= 1u << ((ln & 3) * 8 + k);
                }
            }
            *(float4*)&ctdst[ln * 8]     = make_float4(vals[0], vals[1], vals[2], vals[3]);
            *(float4*)&ctdst[ln * 8 + 4] = make_float4(vals[4], vals[5], vals[6], vals[7]);
        }
    }
    {
        float h1q[8];
        enc01(s, smem + S_PL01, h1q);
        float* c1dst = out + OFF_CT1 + (size_t)t * 128 + nb * 8;
#pragma unroll
        for (int ln = 0; ln < 8; ln++) {
            float vals[8];
#pragma unroll
            for (int k = 0; k < 8; k++) {
                const float* w = smem + S_PW2T + (ln * 8 + k) * 8;
                float a = 0.f;
#pragma unroll
                for (int i = 0; i < 8; i++) a = fmaf(h1q[i], w[i], a);
                vals[k] = a + smem[S_PB2 + ln * 8 + k];
            }
            *(float4*)&c1dst[ln * 8]     = make_float4(vals[0], vals[1], vals[2], vals[3]);
            *(float4*)&c1dst[ln * 8 + 4] = make_float4(vals[4], vals[5], vals[6], vals[7]);
        }
    }
    const bool hasP = (t + 1 < T_LEN);
    float h1p[8];
    {
        float s2 = hasP ? Tin[t + 1] : 0.f;
        enc01(s2, smem + S_PL01, h1p);
    }

    // ---- head phase: half 0 -> lm head; half 1 -> lv head ----
    {
        const float* x = half ? lv : lm;
        float* hdst = out + (half ? OFF_LVP : OFF_LMP);
        head_fn(x + (size_t)t * 8, smem + S_HW1T, smem + S_HB1, smem + S_HW2,
                smem + S_HB2, hdst + (size_t)t * 8);
        head_fn(x + ((size_t)T_LEN + t) * 8, smem + S_HW1T, smem + S_HB1,
                smem + S_HW2, smem + S_HB2, hdst + ((size_t)T_LEN + t) * 8);
    }

    // ---- decode setup: M in regs, V staged to per-thread smem slots ----
    const float4* lm4 = (const float4*)lm;
    const float4* lv4 = (const float4*)lv;
    float2 M[8];
    {
        float4 a0 = lm4[(size_t)t * 2], a1 = lm4[(size_t)t * 2 + 1];
        float4 b0 = lm4[((size_t)T_LEN + t) * 2], b1 = lm4[((size_t)T_LEN + t) * 2 + 1];
        M[0] = make_float2(a0.x, b0.x); M[1] = make_float2(a0.y, b0.y);
        M[2] = make_float2(a0.z, b0.z); M[3] = make_float2(a0.w, b0.w);
        M[4] = make_float2(a1.x, b1.x); M[5] = make_float2(a1.y, b1.y);
        M[6] = make_float2(a1.z, b1.z); M[7] = make_float2(a1.w, b1.w);
        float4 c0 = lv4[(size_t)t * 2], c1 = lv4[(size_t)t * 2 + 1];
        float4 d0 = lv4[((size_t)T_LEN + t) * 2], d1 = lv4[((size_t)T_LEN + t) * 2 + 1];
        // V[k] pair (l0, l1) stored at sv[(2k+l)*HB + tid]
        smem[S_V + (0) * HB + tid] = c0.x;  smem[S_V + (1) * HB + tid] = d0.x;
        smem[S_V + (2) * HB + tid] = c0.y;  smem[S_V + (3) * HB + tid] = d0.y;
        smem[S_V + (4) * HB + tid] = c0.z;  smem[S_V + (5) * HB + tid] = d0.z;
        smem[S_V + (6) * HB + tid] = c0.w;  smem[S_V + (7) * HB + tid] = d0.w;
        smem[S_V + (8) * HB + tid] = c1.x;  smem[S_V + (9) * HB + tid] = d1.x;
        smem[S_V + (10) * HB + tid] = c1.y; smem[S_V + (11) * HB + tid] = d1.y;
        smem[S_V + (12) * HB + tid] = c1.z; smem[S_V + (13) * HB + tid] = d1.z;
        smem[S_V + (14) * HB + tid] = c1.w; smem[S_V + (15) * HB + tid] = d1.w;
    }

    const float2 zz = make_float2(0.f, 0.f);

    for (int ln = 0; ln < 8; ln++) {
        unsigned byte = ((ln < 4 ? mbytes0 : mbytes1) >> ((ln & 3) * 8)) & 0xffu;

        float2 fR[16], fP[16];
#pragma unroll
        for (int k = 0; k < 8; k++) {
            // cp = pre-enc layer2 output at (t+1) for feature (nb+ln)*8+k
            const float* w = smem + S_PW2T + (ln * 8 + k) * 8;
            float cp = 0.f;
#pragma unroll
            for (int i = 0; i < 8; i++) cp = fmaf(h1p[i], w[i], cp);
            cp += smem[S_PB2 + ln * 8 + k];
            float2 cp2 = make_float2(cp, cp);
            float2 Vk = make_float2(smem[S_V + (2 * k) * HB + tid],
                                    smem[S_V + (2 * k + 1) * HB + tid]);
            bool on = (byte >> k) & 1u;
            fR[k]     = on ? M[k] : zz;
            fR[8 + k] = on ? Vk : zz;
            fP[k]     = fmul2(cp2, M[k]);
            fP[8 + k] = fmul2(cp2, Vk);
        }

        float outR = 0.f, outP = 0.f;
        const float4* w4base = (const float4*)(smem + S_W0 + ln * 2048);
        const float2* bw = (const float2*)(smem + S_BW + 2 * ln * 64);
#pragma unroll 2
        for (int j = 0; j < 64; j++) {
            const float4* w4 = w4base + j * 8;
            float2 aR0 = zz, aR1 = zz, aP0 = zz, aP1 = zz;
#pragma unroll
            for (int q = 0; q < 8; q++) {
                float4 wA = w4[q];
                float2 w0p = make_float2(wA.x, wA.y);
                float2 w1p = make_float2(wA.z, wA.w);
                aR0 = ffma2(fR[2 * q],     w0p, aR0);
                aR1 = ffma2(fR[2 * q + 1], w1p, aR1);
                aP0 = ffma2(fP[2 * q],     w0p, aP0);
                aP1 = ffma2(fP[2 * q + 1], w1p, aP1);
            }
            float2 bwj = bw[j];
            float2 sR = fadd2(aR0, aR1);
            float2 sP = fadd2(aP0, aP1);
            float hR = fmaxf(sR.x + sR.y + bwj.x, 0.f);
            float hP = fmaxf(sP.x + sP.y + bwj.x, 0.f);
            outR = fmaf(hR, bwj.y, outR);
            outP = fmaf(hP, bwj.y, outP);
        }
        float be = smem[S_BEFF + ln];
        out[OFF_RECON + (size_t)t * 16 + nb + ln] = fmaxf(outR + be, 0.f);
        if (hasP)
            out[OFF_PRED + (size_t)(t + 1) * 16 + nb + ln] = fmaxf(outP + be, 0.f);
    }
}

// ---------------------------------------------------------------------------
extern "C" void kernel_launch(void* const* d_in, const int* in_sizes, int n_in,
                              void* d_out, int out_size) {
    const float* lm  = (const float*)d_in[0];
    const float* lv  = (const float*)d_in[1];
    const float* Tin = (const float*)d_in[2];
    const float* cw0 = (const float*)d_in[3];
    const float* cb0 = (const float*)d_in[4];
    const float* cw1 = (const float*)d_in[5];
    const float* cb1 = (const float*)d_in[6];
    const float* cw2 = (const float*)d_in[7];
    const float* cb2 = (const float*)d_in[8];
    const float* pw0 = (const float*)d_in[9];
    const float* pb0 = (const float*)d_in[10];
    const float* pw1 = (const float*)d_in[11];
    const float* pb1 = (const float*)d_in[12];
    const float* pw2 = (const float*)d_in[13];
    const float* pb2 = (const float*)d_in[14];
    const float* fmw1 = (const float*)d_in[15];
    const float* fmb1 = (const float*)d_in[16];
    const float* fmw2 = (const float*)d_in[17];
    const float* fmb2 = (const float*)d_in[18];
    const float* fvw1 = (const float*)d_in[19];
    const float* fvb1 = (const float*)d_in[20];
    const float* fvw2 = (const float*)d_in[21];
    const float* fvb2 = (const float*)d_in[22];
    const float* lw0 = (const float*)d_in[23];
    const float* lb0 = (const float*)d_in[24];
    const float* lw1 = (const float*)d_in[25];
    const float* lb1 = (const float*)d_in[26];
    const float* lw2 = (const float*)d_in[27];
    const float* lb2 = (const float*)d_in[28];
    float* out = (float*)d_out;

    cudaFuncSetAttribute(mega_kernel, cudaFuncAttributeMaxDynamicSharedMemorySize,
                         MEGA_SMEM_BYTES);

    prep_kernel<<<1, 1024>>>(lw0, lw1, lw2, lb0, lb1, lb2, out);
    dim3 grid(HGX, 2);
    mega_kernel<<<grid, HB, MEGA_SMEM_BYTES>>>(
        lm, lv, Tin,
        cw0, cb0, cw1, cb1, cw2, cb2,
        pw0, pb0, pw1, pb1, pw2, pb2,
        fmw1, fmb1, fmw2, fmb2,
        fvw1, fvb1, fvw2, fvb2,
        lb0, out);
}